// round 1
// baseline (speedup 1.0000x reference)
#include <cuda_runtime.h>
#include <math.h>

// Problem constants
static constexpr int Bc = 4;
static constexpr int Tc = 10;
static constexpr int Nc = 4096;
static constexpr int Hc = 32;
static constexpr int NHc = Nc * Hc;          // 131072
static constexpr int NCP = 144;              // padded column count (132 real: 128 h + 4 x)
static constexpr int BM = 128;
static constexpr int BKt = 16;
static constexpr int SPLITK = 8;
static constexpr int KCHUNK = Nc / SPLITK;   // 512

// Scratch (device globals; no allocations allowed in kernel_launch)
__device__ float       g_Abase[(size_t)Nc * Nc];        // (spec+eye)/2
__device__ signed char g_thr[(size_t)Nc * Nc];          // first active t (127 = never)
__device__ float       g_C[Nc * NCP];                   // GEMM B-operand
__device__ float       g_Ypart[(size_t)SPLITK * Nc * NCP];
__device__ float       g_gcn1[Bc * Nc * 2 * Hc];        // [b][n][64]
__device__ float       g_gcn2[Bc * Nc * Hc];            // [b][n][32]

__device__ __forceinline__ float sigmoidf_(float x) { return 1.f / (1.f + expf(-x)); }

// ---------------------------------------------------------------------------
// Precompute Abase and integer activation threshold.
// dtwt active at step t  <=>  dtw!=0 && t+1 > (T - ceil(|td|))  <=>  t >= thr (integers)
// ---------------------------------------------------------------------------
__global__ void prep_kernel(const float* __restrict__ dtw, const float* __restrict__ spec,
                            const float* __restrict__ td) {
    size_t i = (size_t)blockIdx.x * blockDim.x + threadIdx.x;
    if (i >= (size_t)Nc * Nc) return;
    int m = (int)(i >> 12), n = (int)(i & (Nc - 1));
    g_Abase[i] = 0.5f * (spec[i] + (m == n ? 1.f : 0.f));
    float d = dtw[i];
    int thr;
    if (d != 0.f) {
        float ti = (float)Tc - ceilf(fabsf(td[i]));  // SR = 1.0
        thr = (int)ti;
        if (thr > 126) thr = 126;
        if (thr < -128) thr = -128;
    } else {
        thr = 127;  // never active
    }
    g_thr[i] = (signed char)thr;
}

__global__ void zero_kernel() {
    int i = blockIdx.x * blockDim.x + threadIdx.x;
    if (i < Bc * Nc * 2 * Hc) g_gcn1[i] = 0.f;
    if (i < Bc * Nc * Hc) g_gcn2[i] = 0.f;
}

// ---------------------------------------------------------------------------
// Build C (the [N,132] RHS). cols 0..127: h (b*32+k), cols 128..131: x per batch.
// ---------------------------------------------------------------------------
__global__ void buildC1_kernel(const float* __restrict__ inputs, const float* __restrict__ states,
                               int t) {
    int i = blockIdx.x * blockDim.x + threadIdx.x;
    if (i >= Nc * NCP) return;
    int n = i / NCP, c = i - n * NCP;
    float v = 0.f;
    if (c < 128) {
        int b = c >> 5, k = c & 31;
        v = states[((size_t)t * Bc + b) * NHc + n * Hc + k];
    } else if (c < 132) {
        int b = c - 128;
        v = inputs[((size_t)b * Tc + t) * Nc + n];
    }
    g_C[(size_t)n * NCP + c] = v;
}

// C2 = [x, r .* h] with r from torch.chunk-style flat split of sigmoid(gcn1)
__global__ void buildC2_kernel(const float* __restrict__ inputs, const float* __restrict__ states,
                               int t) {
    int i = blockIdx.x * blockDim.x + threadIdx.x;
    if (i >= Nc * NCP) return;
    int n = i / NCP, c = i - n * NCP;
    float v = 0.f;
    if (c < 128) {
        int b = c >> 5, k = c & 31;
        // flat idx j = n*32+k -> gcn1[b][n>>1][(n&1)*32+k]
        float g = g_gcn1[((size_t)b * Nc + (n >> 1)) * 64 + (n & 1) * 32 + k];
        v = sigmoidf_(g) * states[((size_t)t * Bc + b) * NHc + n * Hc + k];
    } else if (c < 132) {
        int b = c - 128;
        v = inputs[((size_t)b * Tc + t) * Nc + n];
    }
    g_C[(size_t)n * NCP + c] = v;
}

// ---------------------------------------------------------------------------
// GEMM: Ypart[s][m][c] = sum_{n in split s} A_t[m,n] * C[n][c]
// A built on the fly: t<9:  Abase + (t>=thr ? 0.5*dtw : 0)
//                     t==9: (2*Abase + lap + (t>=thr ? dtw : 0)) / 3
// ---------------------------------------------------------------------------
__global__ void __launch_bounds__(256, 2)
gemm_kernel(const float* __restrict__ dtw, const float* __restrict__ lap, int t, int finalstep) {
    __shared__ float As[BKt][BM + 4];    // [k][m], padded
    __shared__ float Cs[BKt][NCP + 4];   // [k][c], padded

    int m0 = blockIdx.x * BM;
    int s = blockIdx.y;
    int tid = threadIdx.x;
    int ct = tid & 15, rt = tid >> 4;

    float acc[8][8];
#pragma unroll
    for (int r = 0; r < 8; r++)
#pragma unroll
        for (int j = 0; j < 8; j++) acc[r][j] = 0.f;
    float xacc0 = 0.f, xacc1 = 0.f;
    int xrow = rt * 8 + (ct >> 1);   // local row for the x-columns
    int xb = (ct & 1) * 2;           // batch pair base

    const int kbeg = s * KCHUNK;
    for (int kk = kbeg; kk < kbeg + KCHUNK; kk += BKt) {
        __syncthreads();
        // Load + build A tile: 128 rows x 16 k
#pragma unroll
        for (int i = 0; i < 2; i++) {
            int qi = tid + i * 256;          // 0..511 quad index
            int ml = qi >> 2;                // 0..127
            int kq = (qi & 3) << 2;          // 0,4,8,12
            size_t g = (size_t)(m0 + ml) * Nc + kk + kq;
            float4 ab = *(const float4*)(g_Abase + g);
            float4 dw = *(const float4*)(dtw + g);
            char4 tq = *(const char4*)(g_thr + g);
            float a0, a1, a2, a3;
            if (!finalstep) {
                a0 = ab.x + (t >= (int)tq.x ? 0.5f * dw.x : 0.f);
                a1 = ab.y + (t >= (int)tq.y ? 0.5f * dw.y : 0.f);
                a2 = ab.z + (t >= (int)tq.z ? 0.5f * dw.z : 0.f);
                a3 = ab.w + (t >= (int)tq.w ? 0.5f * dw.w : 0.f);
            } else {
                const float inv3 = (1.f / 3.f);
                float4 lp = *(const float4*)(lap + g);
                a0 = (2.f * ab.x + lp.x + (t >= (int)tq.x ? dw.x : 0.f)) * inv3;
                a1 = (2.f * ab.y + lp.y + (t >= (int)tq.y ? dw.y : 0.f)) * inv3;
                a2 = (2.f * ab.z + lp.z + (t >= (int)tq.z ? dw.z : 0.f)) * inv3;
                a3 = (2.f * ab.w + lp.w + (t >= (int)tq.w ? dw.w : 0.f)) * inv3;
            }
            As[kq + 0][ml] = a0;
            As[kq + 1][ml] = a1;
            As[kq + 2][ml] = a2;
            As[kq + 3][ml] = a3;
        }
        // Load C tile: 16 rows x 144 cols = 576 float4
#pragma unroll
        for (int i = 0; i < 3; i++) {
            int qi = tid + i * 256;
            if (qi < (BKt * NCP) / 4) {
                int kl = qi / (NCP / 4);
                int c4 = qi - kl * (NCP / 4);
                float4 v = *(const float4*)(g_C + (size_t)(kk + kl) * NCP + c4 * 4);
                *(float4*)(&Cs[kl][c4 * 4]) = v;
            }
        }
        __syncthreads();

#pragma unroll 4
        for (int k = 0; k < BKt; k++) {
            float af[8], cf[8];
            *(float4*)(af)     = *(const float4*)(&As[k][rt * 8]);
            *(float4*)(af + 4) = *(const float4*)(&As[k][rt * 8 + 4]);
            *(float4*)(cf)     = *(const float4*)(&Cs[k][ct * 8]);
            *(float4*)(cf + 4) = *(const float4*)(&Cs[k][ct * 8 + 4]);
            float ax = As[k][xrow];
            float2 xv = *(const float2*)(&Cs[k][128 + xb]);
#pragma unroll
            for (int r = 0; r < 8; r++)
#pragma unroll
                for (int j = 0; j < 8; j++) acc[r][j] += af[r] * cf[j];
            xacc0 += ax * xv.x;
            xacc1 += ax * xv.y;
        }
    }

    float* yp = g_Ypart + ((size_t)s * Nc + m0) * NCP;
#pragma unroll
    for (int r = 0; r < 8; r++) {
        int row = rt * 8 + r;
        *(float4*)(yp + (size_t)row * NCP + ct * 8) =
            make_float4(acc[r][0], acc[r][1], acc[r][2], acc[r][3]);
        *(float4*)(yp + (size_t)row * NCP + ct * 8 + 4) =
            make_float4(acc[r][4], acc[r][5], acc[r][6], acc[r][7]);
    }
    *(float2*)(yp + (size_t)xrow * NCP + 128 + xb) = make_float2(xacc0, xacc1);
}

// ---------------------------------------------------------------------------
// Reduce split-K partials, apply the small [33 -> out] weight, accumulate gcn.
// One warp per (b, n).
// ---------------------------------------------------------------------------
__global__ void reduce1_kernel(const float* __restrict__ W1, const float* __restrict__ b1) {
    __shared__ float W1s[33 * 64];
    __shared__ float b1s[64];
    int tid = threadIdx.x;
    for (int i = tid; i < 33 * 64; i += 256) W1s[i] = W1[i];
    if (tid < 64) b1s[tid] = b1[tid];
    __syncthreads();

    int w = blockIdx.x * 8 + (tid >> 5);
    int lane = tid & 31;
    int b = w >> 12;
    int n = w & (Nc - 1);

    float ys = 0.f, yx = 0.f;
#pragma unroll
    for (int s = 0; s < SPLITK; s++) {
        const float* yp = g_Ypart + ((size_t)s * Nc + n) * NCP;
        ys += yp[b * Hc + lane];
        yx += yp[128 + b];
    }
    float acc0 = yx * W1s[lane];
    float acc1 = yx * W1s[lane + 32];
#pragma unroll
    for (int j = 0; j < 32; j++) {
        float yj = __shfl_sync(0xffffffffu, ys, j);
        acc0 += yj * W1s[(j + 1) * 64 + lane];
        acc1 += yj * W1s[(j + 1) * 64 + lane + 32];
    }
    size_t o = ((size_t)b * Nc + n) * 64;
    g_gcn1[o + lane] += acc0 + b1s[lane];
    g_gcn1[o + lane + 32] += acc1 + b1s[lane + 32];
}

__global__ void reduce2_kernel(const float* __restrict__ W2, const float* __restrict__ b2) {
    __shared__ float W2s[33 * 32];
    __shared__ float b2s[32];
    int tid = threadIdx.x;
    for (int i = tid; i < 33 * 32; i += 256) W2s[i] = W2[i];
    if (tid < 32) b2s[tid] = b2[tid];
    __syncthreads();

    int w = blockIdx.x * 8 + (tid >> 5);
    int lane = tid & 31;
    int b = w >> 12;
    int n = w & (Nc - 1);

    float ys = 0.f, yx = 0.f;
#pragma unroll
    for (int s = 0; s < SPLITK; s++) {
        const float* yp = g_Ypart + ((size_t)s * Nc + n) * NCP;
        ys += yp[b * Hc + lane];
        yx += yp[128 + b];
    }
    float acc = yx * W2s[lane];
#pragma unroll
    for (int j = 0; j < 32; j++) {
        float yj = __shfl_sync(0xffffffffu, ys, j);
        acc += yj * W2s[(j + 1) * 32 + lane];
    }
    g_gcn2[((size_t)b * Nc + n) * 32 + lane] += acc + b2s[lane];
}

// h_new = u .* h_{T-1} + (1-u) .* tanh(gcn2), u = sigmoid(second flat half of gcn1)
__global__ void final_kernel(const float* __restrict__ states, float* __restrict__ out) {
    int i = blockIdx.x * blockDim.x + threadIdx.x;
    if (i >= Bc * NHc) return;
    int b = i / NHc;
    int rem = i - b * NHc;
    int n = rem >> 5, k = rem & 31;
    // flat idx j = N*32 + n*32 + k -> gcn1[b][2048 + (n>>1)][(n&1)*32 + k]
    float g1 = g_gcn1[((size_t)b * Nc + 2048 + (n >> 1)) * 64 + (n & 1) * 32 + k];
    float u = sigmoidf_(g1);
    float c = tanhf(g_gcn2[i]);
    float h = states[((size_t)(Tc - 1) * Bc + b) * NHc + rem];
    out[i] = u * h + (1.f - u) * c;
}

// ---------------------------------------------------------------------------
extern "C" void kernel_launch(void* const* d_in, const int* in_sizes, int n_in,
                              void* d_out, int out_size) {
    const float* inputs = (const float*)d_in[0];  // [B,T,N]
    const float* states = (const float*)d_in[1];  // [T,B,N*H]
    const float* dtw    = (const float*)d_in[2];  // [N,N]
    const float* spec   = (const float*)d_in[3];  // [N,N]
    const float* lap    = (const float*)d_in[4];  // [N,N]
    const float* td     = (const float*)d_in[5];  // [N,N]
    const float* W1     = (const float*)d_in[6];  // [33,64]
    const float* b1     = (const float*)d_in[7];  // [64]
    const float* W2     = (const float*)d_in[8];  // [33,32]
    const float* b2     = (const float*)d_in[9];  // [32]
    float* out = (float*)d_out;

    prep_kernel<<<(int)(((size_t)Nc * Nc + 255) / 256), 256>>>(dtw, spec, td);
    zero_kernel<<<(Bc * Nc * 2 * Hc + 255) / 256, 256>>>();

    for (int t = 0; t < Tc; t++) {
        int fin = (t == Tc - 1) ? 1 : 0;
        buildC1_kernel<<<(Nc * NCP + 255) / 256, 256>>>(inputs, states, t);
        gemm_kernel<<<dim3(Nc / BM, SPLITK), 256>>>(dtw, lap, t, fin);
        reduce1_kernel<<<(Bc * Nc) / 8, 256>>>(W1, b1);
        buildC2_kernel<<<(Nc * NCP + 255) / 256, 256>>>(inputs, states, t);
        gemm_kernel<<<dim3(Nc / BM, SPLITK), 256>>>(dtw, lap, t, fin);
        reduce2_kernel<<<(Bc * Nc) / 8, 256>>>(W2, b2);
    }
    final_kernel<<<(Bc * NHc + 255) / 256, 256>>>(states, out);
}

// round 2
// speedup vs baseline: 1.8895x; 1.8895x over previous
#include <cuda_runtime.h>
#include <cuda_bf16.h>
#include <math.h>

static constexpr int Bc = 4;
static constexpr int Tc = 10;
static constexpr int Nc = 4096;
static constexpr int Hc = 32;
static constexpr int NHc = Nc * Hc;          // 131072
static constexpr int NCP = 136;              // padded cols (132 used: 128 h + 4 x)
static constexpr int NT = NCP / 8;           // 17 n-tiles per warp
static constexpr int BM = 128;
static constexpr int KC = 32;                // k per smem stage
static constexpr int KSPLIT = 4;
static constexpr int KRANGE = Nc / KSPLIT;   // 1024
static constexpr int SA = 40;                // smem row stride (halfs), conflict-free

// ---- device scratch (no allocations allowed) ----
__device__ float         g_Abase[(size_t)Nc * Nc];              // (spec+eye)/2
__device__ signed char   g_thr[(size_t)Nc * Nc];                // activation step
__device__ __nv_bfloat16 g_C1h[(size_t)Tc * NCP * Nc];
__device__ __nv_bfloat16 g_C1l[(size_t)Tc * NCP * Nc];
__device__ __nv_bfloat16 g_C2h[(size_t)Tc * NCP * Nc];
__device__ __nv_bfloat16 g_C2l[(size_t)Tc * NCP * Nc];
__device__ float         g_Y[(size_t)KSPLIT * Tc * Nc * NCP];   // 89 MB
__device__ float         g_RH[(size_t)Tc * Bc * Nc * Hc];       // r .* h
__device__ float         g_g1fin[(size_t)Bc * Nc * 64];         // final gcn1

__device__ __forceinline__ float sigmoidf_(float x) { return 1.f / (1.f + expf(-x)); }

// ---------------------------------------------------------------------------
__global__ void prep_kernel(const float* __restrict__ dtw, const float* __restrict__ spec,
                            const float* __restrict__ td) {
    size_t i = (size_t)blockIdx.x * blockDim.x + threadIdx.x;
    if (i >= (size_t)Nc * Nc) return;
    int m = (int)(i >> 12), n = (int)(i & (Nc - 1));
    g_Abase[i] = 0.5f * (spec[i] + (m == n ? 1.f : 0.f));
    float d = dtw[i];
    int thr;
    if (d != 0.f) {
        float ti = (float)Tc - ceilf(fabsf(td[i]));  // SR = 1.0
        thr = (int)ti;
        if (thr > 126) thr = 126;
        if (thr < -128) thr = -128;
    } else {
        thr = 127;
    }
    g_thr[i] = (signed char)thr;
}

// ---------------------------------------------------------------------------
// Build C1 for all t: layout [t][c][n] bf16 hi/lo. c<128: h (b*32+k); 128..131: x; pad 0.
// ---------------------------------------------------------------------------
__global__ void buildC1_kernel(const float* __restrict__ inputs, const float* __restrict__ states) {
    int i = blockIdx.x * blockDim.x + threadIdx.x;
    if (i >= Tc * NCP * Nc) return;
    int n = i & (Nc - 1);
    int rc = i >> 12;                 // t*NCP + c
    int t = rc / NCP, c = rc - t * NCP;
    float v = 0.f;
    if (c < 128) {
        int b = c >> 5, k = c & 31;
        v = states[((size_t)t * Bc + b) * NHc + (size_t)n * Hc + k];
    } else if (c < 132) {
        int b = c - 128;
        v = inputs[((size_t)b * Tc + t) * Nc + n];
    }
    __nv_bfloat16 hi = __float2bfloat16(v);
    g_C1h[i] = hi;
    g_C1l[i] = __float2bfloat16(v - __bfloat162float(hi));
}

__global__ void buildC2_kernel(const float* __restrict__ inputs) {
    int i = blockIdx.x * blockDim.x + threadIdx.x;
    if (i >= Tc * NCP * Nc) return;
    int n = i & (Nc - 1);
    int rc = i >> 12;
    int t = rc / NCP, c = rc - t * NCP;
    float v = 0.f;
    if (c < 128) {
        int b = c >> 5, k = c & 31;
        v = g_RH[(((size_t)t * Bc + b) * Nc + n) * Hc + k];
    } else if (c < 132) {
        int b = c - 128;
        v = inputs[((size_t)b * Tc + t) * Nc + n];
    }
    __nv_bfloat16 hi = __float2bfloat16(v);
    g_C2h[i] = hi;
    g_C2l[i] = __float2bfloat16(v - __bfloat162float(hi));
}

// ---------------------------------------------------------------------------
// bf16 split-3 MMA GEMM: Y[s][t][m][c] = sum_{k in split s} A_t[m,k] * C_t[k][c]
// ---------------------------------------------------------------------------
__device__ __forceinline__ void mma16816(float* d, const unsigned* a, unsigned b0, unsigned b1) {
    asm volatile(
        "mma.sync.aligned.m16n8k16.row.col.f32.bf16.bf16.f32 "
        "{%0,%1,%2,%3}, {%4,%5,%6,%7}, {%8,%9}, {%0,%1,%2,%3};"
        : "+f"(d[0]), "+f"(d[1]), "+f"(d[2]), "+f"(d[3])
        : "r"(a[0]), "r"(a[1]), "r"(a[2]), "r"(a[3]), "r"(b0), "r"(b1));
}

__global__ void __launch_bounds__(256, 2)
gemm_kernel(const float* __restrict__ dtw, const float* __restrict__ lap, int phase) {
    __shared__ __nv_bfloat16 Ah[BM][SA], Al[BM][SA];
    __shared__ __nv_bfloat16 Bh[NCP][SA], Bl[NCP][SA];

    const int m0 = blockIdx.x * BM;
    const int t = blockIdx.y;
    const int kbeg = blockIdx.z * KRANGE;
    const bool fin = (t == Tc - 1);
    const int tid = threadIdx.x;
    const int warp = tid >> 5, lane = tid & 31;
    const int g = lane >> 2, tg = lane & 3;
    const int mr = warp * 16;

    const __nv_bfloat16* Cth = (phase ? g_C2h : g_C1h) + (size_t)t * NCP * Nc;
    const __nv_bfloat16* Ctl = (phase ? g_C2l : g_C1l) + (size_t)t * NCP * Nc;

    float acc[NT][4];
#pragma unroll
    for (int i = 0; i < NT; i++)
#pragma unroll
        for (int j = 0; j < 4; j++) acc[i][j] = 0.f;

    for (int k0 = kbeg; k0 < kbeg + KRANGE; k0 += KC) {
        __syncthreads();
        // Build A tile (hi/lo bf16) from Abase/dtw/thr (+lap on final step)
#pragma unroll
        for (int it = 0; it < 4; ++it) {
            int slot = tid + it * 256;          // 1024 slots: 128 rows x 8 float4
            int row = slot >> 3;
            int kq = (slot & 7) * 4;
            size_t gi = (size_t)(m0 + row) * Nc + k0 + kq;
            float4 ab = *(const float4*)(g_Abase + gi);
            float4 dw = *(const float4*)(dtw + gi);
            char4 tq = *(const char4*)(g_thr + gi);
            float a[4];
            if (!fin) {
                a[0] = ab.x + (t >= (int)tq.x ? 0.5f * dw.x : 0.f);
                a[1] = ab.y + (t >= (int)tq.y ? 0.5f * dw.y : 0.f);
                a[2] = ab.z + (t >= (int)tq.z ? 0.5f * dw.z : 0.f);
                a[3] = ab.w + (t >= (int)tq.w ? 0.5f * dw.w : 0.f);
            } else {
                const float inv3 = (1.f / 3.f);
                float4 lp = *(const float4*)(lap + gi);
                a[0] = (2.f * ab.x + lp.x + (t >= (int)tq.x ? dw.x : 0.f)) * inv3;
                a[1] = (2.f * ab.y + lp.y + (t >= (int)tq.y ? dw.y : 0.f)) * inv3;
                a[2] = (2.f * ab.z + lp.z + (t >= (int)tq.z ? dw.z : 0.f)) * inv3;
                a[3] = (2.f * ab.w + lp.w + (t >= (int)tq.w ? dw.w : 0.f)) * inv3;
            }
#pragma unroll
            for (int j = 0; j < 4; j++) {
                __nv_bfloat16 hi = __float2bfloat16(a[j]);
                Ah[row][kq + j] = hi;
                Al[row][kq + j] = __float2bfloat16(a[j] - __bfloat162float(hi));
            }
        }
        // Load C tile: NCP rows x 32 k halfs (hi and lo), uint4 = 8 halfs
#pragma unroll
        for (int it = 0; it < 3; ++it) {
            int slot = tid + it * 256;
            if (slot < NCP * 4) {
                int row = slot >> 2;
                int kq = (slot & 3) * 8;
                *(uint4*)&Bh[row][kq] = *(const uint4*)(Cth + (size_t)row * Nc + k0 + kq);
                *(uint4*)&Bl[row][kq] = *(const uint4*)(Ctl + (size_t)row * Nc + k0 + kq);
            }
        }
        __syncthreads();

#pragma unroll
        for (int ks = 0; ks < 2; ++ks) {
            const int ko = ks * 16 + tg * 2;
            unsigned ah[4], al[4];
            ah[0] = *(const unsigned*)&Ah[mr + g][ko];
            ah[1] = *(const unsigned*)&Ah[mr + g + 8][ko];
            ah[2] = *(const unsigned*)&Ah[mr + g][ko + 8];
            ah[3] = *(const unsigned*)&Ah[mr + g + 8][ko + 8];
            al[0] = *(const unsigned*)&Al[mr + g][ko];
            al[1] = *(const unsigned*)&Al[mr + g + 8][ko];
            al[2] = *(const unsigned*)&Al[mr + g][ko + 8];
            al[3] = *(const unsigned*)&Al[mr + g + 8][ko + 8];
#pragma unroll
            for (int nt = 0; nt < NT; ++nt) {
                unsigned bh0 = *(const unsigned*)&Bh[nt * 8 + g][ko];
                unsigned bh1 = *(const unsigned*)&Bh[nt * 8 + g][ko + 8];
                unsigned bl0 = *(const unsigned*)&Bl[nt * 8 + g][ko];
                unsigned bl1 = *(const unsigned*)&Bl[nt * 8 + g][ko + 8];
                mma16816(acc[nt], ah, bh0, bh1);
                mma16816(acc[nt], ah, bl0, bl1);
                mma16816(acc[nt], al, bh0, bh1);
            }
        }
    }

    float* Yt = g_Y + ((size_t)(blockIdx.z * Tc + t) * Nc + m0) * NCP;
#pragma unroll
    for (int nt = 0; nt < NT; ++nt) {
        int col = nt * 8 + tg * 2;
        *(float2*)(Yt + (size_t)(mr + g) * NCP + col) = make_float2(acc[nt][0], acc[nt][1]);
        *(float2*)(Yt + (size_t)(mr + g + 8) * NCP + col) = make_float2(acc[nt][2], acc[nt][3]);
    }
}

// ---------------------------------------------------------------------------
// Gate: per (b, m) warp — prefix-accumulate gcn1 over t, emit r.*h for C2,
// store final gcn1 (for u).
// ---------------------------------------------------------------------------
__global__ void gate_kernel(const float* __restrict__ W1, const float* __restrict__ b1,
                            const float* __restrict__ states) {
    __shared__ float W1s[33 * 64];
    __shared__ float b1s[64];
    int tid = threadIdx.x;
    for (int i = tid; i < 33 * 64; i += 256) W1s[i] = W1[i];
    if (tid < 64) b1s[tid] = b1[tid];
    __syncthreads();

    int w = blockIdx.x * 8 + (tid >> 5);
    int lane = tid & 31;
    int b = w >> 12, m = w & (Nc - 1);

    float acc0 = 0.f, acc1 = 0.f;
    for (int t = 0; t < Tc; t++) {
        float ys = 0.f, yx = 0.f;
#pragma unroll
        for (int s = 0; s < KSPLIT; s++) {
            const float* yp = g_Y + ((size_t)(s * Tc + t) * Nc + m) * NCP;
            ys += yp[b * Hc + lane];
            yx += yp[128 + b];
        }
        acc0 += yx * W1s[lane] + b1s[lane];
        acc1 += yx * W1s[lane + 32] + b1s[lane + 32];
#pragma unroll
        for (int j = 0; j < 32; j++) {
            float yj = __shfl_sync(0xffffffffu, ys, j);
            acc0 += yj * W1s[(j + 1) * 64 + lane];
            acc1 += yj * W1s[(j + 1) * 64 + lane + 32];
        }
        if (m < Nc / 2) {
            // flat split: gcn1[b][m][0..31] -> r for row 2m; [32..63] -> row 2m+1
            float r0 = sigmoidf_(acc0);
            float r1 = sigmoidf_(acc1);
            int n0 = 2 * m;
            size_t hidx = ((size_t)t * Bc + b) * NHc + (size_t)n0 * Hc + lane;
            size_t ridx = (((size_t)t * Bc + b) * Nc + n0) * Hc + lane;
            g_RH[ridx] = r0 * states[hidx];
            g_RH[ridx + Hc] = r1 * states[hidx + Hc];
        }
    }
    size_t o = ((size_t)b * Nc + m) * 64;
    g_g1fin[o + lane] = acc0;
    g_g1fin[o + 32 + lane] = acc1;
}

// ---------------------------------------------------------------------------
// Final: gcn2 = (sum_t Y2_t) @ W2 + 10*b2; h_new = u*h9 + (1-u)*tanh(gcn2)
// ---------------------------------------------------------------------------
__global__ void final_kernel(const float* __restrict__ W2, const float* __restrict__ b2,
                             const float* __restrict__ states, float* __restrict__ out) {
    __shared__ float W2s[33 * 32];
    __shared__ float b2s[32];
    int tid = threadIdx.x;
    for (int i = tid; i < 33 * 32; i += 256) W2s[i] = W2[i];
    if (tid < 32) b2s[tid] = b2[tid];
    __syncthreads();

    int w = blockIdx.x * 8 + (tid >> 5);
    int lane = tid & 31;
    int b = w >> 12, n = w & (Nc - 1);

    float ys = 0.f, yx = 0.f;
    for (int t = 0; t < Tc; t++) {
#pragma unroll
        for (int s = 0; s < KSPLIT; s++) {
            const float* yp = g_Y + ((size_t)(s * Tc + t) * Nc + n) * NCP;
            ys += yp[b * Hc + lane];
            yx += yp[128 + b];
        }
    }
    float acc = yx * W2s[lane] + (float)Tc * b2s[lane];
#pragma unroll
    for (int j = 0; j < 32; j++) {
        float yj = __shfl_sync(0xffffffffu, ys, j);
        acc += yj * W2s[(j + 1) * 32 + lane];
    }
    float cc = tanhf(acc);
    // u from second flat half of final gcn1
    float g1 = g_g1fin[((size_t)b * Nc + (Nc / 2) + (n >> 1)) * 64 + (n & 1) * 32 + lane];
    float u = sigmoidf_(g1);
    float h = states[((size_t)(Tc - 1) * Bc + b) * NHc + (size_t)n * Hc + lane];
    out[(size_t)b * NHc + (size_t)n * Hc + lane] = u * h + (1.f - u) * cc;
}

// ---------------------------------------------------------------------------
extern "C" void kernel_launch(void* const* d_in, const int* in_sizes, int n_in,
                              void* d_out, int out_size) {
    const float* inputs = (const float*)d_in[0];
    const float* states = (const float*)d_in[1];
    const float* dtw    = (const float*)d_in[2];
    const float* spec   = (const float*)d_in[3];
    const float* lap    = (const float*)d_in[4];
    const float* td     = (const float*)d_in[5];
    const float* W1     = (const float*)d_in[6];
    const float* b1     = (const float*)d_in[7];
    const float* W2     = (const float*)d_in[8];
    const float* b2     = (const float*)d_in[9];
    float* out = (float*)d_out;

    prep_kernel<<<(int)(((size_t)Nc * Nc + 255) / 256), 256>>>(dtw, spec, td);
    buildC1_kernel<<<(Tc * NCP * Nc + 255) / 256, 256>>>(inputs, states);
    gemm_kernel<<<dim3(Nc / BM, Tc, KSPLIT), 256>>>(dtw, lap, 0);
    gate_kernel<<<(Bc * Nc) / 8, 256>>>(W1, b1, states);
    buildC2_kernel<<<(Tc * NCP * Nc + 255) / 256, 256>>>(inputs);
    gemm_kernel<<<dim3(Nc / BM, Tc, KSPLIT), 256>>>(dtw, lap, 1);
    final_kernel<<<(Bc * Nc) / 8, 256>>>(W2, b2, states, out);
}